// round 12
// baseline (speedup 1.0000x reference)
#include <cuda_runtime.h>
#include <cstdint>

#define EMBED 1024
#define HEADS 16
#define DK 64
#define BATCH 2
#define SEQ 2048
#define MTOT (BATCH*SEQ)   // 4096

// Q pre-scale: 1/sqrt(64) * log2(e) folded into the Q projection epilogue
#define QSCALE 0.1803368801111f

// ---------------------------------------------------------------------------
// Scratch
// ---------------------------------------------------------------------------
__device__ float g_q[(size_t)BATCH*HEADS*SEQ*DK];
__device__ float g_k[(size_t)BATCH*HEADS*SEQ*DK];
__device__ float g_v[(size_t)BATCH*HEADS*DK*SEQ];   // transposed [bh][d][s]
__device__ float g_att[(size_t)MTOT*EMBED];
__device__ float g_wq[(size_t)EMBED*EMBED];
__device__ float g_wk[(size_t)EMBED*EMBED];
__device__ float g_wv[(size_t)EMBED*EMBED];
__device__ float g_wo[(size_t)EMBED*EMBED];
__device__ float g_xq[(size_t)MTOT*EMBED];
__device__ float g_xk[(size_t)MTOT*EMBED];
__device__ float g_xv[(size_t)MTOT*EMBED];

// ---------------------------------------------------------------------------
// Helpers
// ---------------------------------------------------------------------------
__device__ __forceinline__ uint32_t smem_to_u32(const void* p) {
    uint32_t a;
    asm("{ .reg .u64 t; cvta.to.shared.u64 t, %1; cvt.u32.u64 %0, t; }"
        : "=r"(a) : "l"(p));
    return a;
}
__device__ __forceinline__ uint32_t f2tf32(float x) {
    uint32_t u;
    asm("cvt.rna.tf32.f32 %0, %1;" : "=r"(u) : "f"(x));
    return u;
}
__device__ __forceinline__ float ex2f(float x) {
    float y;
    asm("ex2.approx.f32 %0, %1;" : "=f"(y) : "f"(x));
    return y;
}
__device__ __forceinline__ void mma_tf32_16x8x8(float c[4], const uint32_t a[4],
                                                const uint32_t b[2]) {
    asm("mma.sync.aligned.m16n8k8.row.col.f32.tf32.tf32.f32 "
        "{%0,%1,%2,%3}, {%4,%5,%6,%7}, {%8,%9}, {%0,%1,%2,%3};"
        : "+f"(c[0]), "+f"(c[1]), "+f"(c[2]), "+f"(c[3])
        : "r"(a[0]), "r"(a[1]), "r"(a[2]), "r"(a[3]), "r"(b[0]), "r"(b[1]));
}
__device__ __forceinline__ void cp16(uint32_t dst, const void* src) {
    asm volatile("cp.async.cg.shared.global [%0], [%1], 16;" :: "r"(dst), "l"(src));
}
#define CP_COMMIT() asm volatile("cp.async.commit_group;" ::: "memory")
#define CP_WAIT1()  asm volatile("cp.async.wait_group 1;" ::: "memory")
#define CP_WAIT0()  asm volatile("cp.async.wait_group 0;" ::: "memory")

// within-8 permutation: original index b -> slot; pairs (b, b+4) land at (2b, 2b+1)
__device__ __host__ __forceinline__ int sig8(int b) { return ((b & 3) << 1) | (b >> 2); }

// ---------------------------------------------------------------------------
// Pre-passes: fp32 -> tf32 (rna) + sig8 k-axis permutation
// ---------------------------------------------------------------------------
__global__ void cvt4_kernel(const float* __restrict__ wq, const float* __restrict__ wk,
                            const float* __restrict__ wv, const float* __restrict__ wo) {
    const int sel = blockIdx.y;
    const float* in = (sel == 0) ? wq : (sel == 1) ? wk : (sel == 2) ? wv : wo;
    float* out = (sel == 0) ? g_wq : (sel == 1) ? g_wk : (sel == 2) ? g_wv : g_wo;
    size_t i = ((size_t)blockIdx.x * 256 + threadIdx.x) * 4;
    float4 v = *(const float4*)(in + i);
    size_t base = i & ~7ULL;
    int off = (int)(i & 7);
    *(uint32_t*)(out + base + sig8(off + 0)) = f2tf32(v.x);
    *(uint32_t*)(out + base + sig8(off + 1)) = f2tf32(v.y);
    *(uint32_t*)(out + base + sig8(off + 2)) = f2tf32(v.z);
    *(uint32_t*)(out + base + sig8(off + 3)) = f2tf32(v.w);
}

__global__ void prep_act_kernel(const float* __restrict__ q, const float* __restrict__ k,
                                const float* __restrict__ v) {
    const int sel = blockIdx.y;
    const float* in = (sel == 0) ? q : (sel == 1) ? k : v;
    float* out = (sel == 0) ? g_xq : (sel == 1) ? g_xk : g_xv;
    size_t i = ((size_t)blockIdx.x * 256 + threadIdx.x) * 4;
    float4 val = *(const float4*)(in + i);
    size_t base = i & ~7ULL;
    int off = (int)(i & 7);
    *(uint32_t*)(out + base + sig8(off + 0)) = f2tf32(val.x);
    *(uint32_t*)(out + base + sig8(off + 1)) = f2tf32(val.y);
    *(uint32_t*)(out + base + sig8(off + 2)) = f2tf32(val.z);
    *(uint32_t*)(out + base + sig8(off + 3)) = f2tf32(val.w);
}

// ---------------------------------------------------------------------------
// tf32 mma.sync GEMM body. A and W pre-rounded + k-permuted -> LDS.64 frags.
// mode: 0 = plain + bias; 1 = Q (scatter + d-perm, *QSCALE, tf32);
//       2 = K (scatter + d-perm, tf32); 3 = V (transposed [bh][d][s], s-perm, tf32)
// ---------------------------------------------------------------------------
#define BM 128
#define BN 128
#define BK 32
#define LDT 40
#define TILE_F (BM * LDT)
#define GCHUNKS (EMBED / BK)

__device__ __forceinline__ void load_chunk(const float* __restrict__ A,
                                           const float* __restrict__ W,
                                           int m0, int n0, int c,
                                           uint32_t sa, uint32_t sb, int tid) {
    const float* Ab = A + (size_t)m0 * EMBED + c * BK;
    #pragma unroll
    for (int it = 0; it < 4; it++) {
        int seg = tid + it * 256;
        int r = seg >> 3, s8 = seg & 7;
        cp16(sa + r * (LDT * 4) + s8 * 16, Ab + (size_t)r * EMBED + s8 * 4);
    }
    const float* Wb = W + (size_t)n0 * EMBED + c * BK;
    #pragma unroll
    for (int it = 0; it < 4; it++) {
        int seg = tid + it * 256;
        int r = seg >> 3, s8 = seg & 7;
        cp16(sb + r * (LDT * 4) + s8 * 16, Wb + (size_t)r * EMBED + s8 * 4);
    }
    CP_COMMIT();
}

__device__ __forceinline__ void gemm_body(
    const float* __restrict__ A, const float* __restrict__ W,
    float* __restrict__ O, const float* __restrict__ bias, int mode,
    float* smg, int bx, int by)
{
    float* As[2] = { smg,            smg + 2 * TILE_F };
    float* Bs[2] = { smg + TILE_F,   smg + 3 * TILE_F };
    const uint32_t sa_u[2] = { smem_to_u32(As[0]), smem_to_u32(As[1]) };
    const uint32_t sb_u[2] = { smem_to_u32(Bs[0]), smem_to_u32(Bs[1]) };

    const int tid = threadIdx.x;
    const int lane = tid & 31;
    const int warp = tid >> 5;
    const int wm = warp >> 1;
    const int wn = warp & 1;
    const int qrow = lane >> 2;
    const int qcol = lane & 3;
    const int m0 = by * BM;
    const int n0 = bx * BN;

    float c[2][8][4];
    #pragma unroll
    for (int mt = 0; mt < 2; mt++)
        #pragma unroll
        for (int nt = 0; nt < 8; nt++)
            #pragma unroll
            for (int r = 0; r < 4; r++) c[mt][nt][r] = 0.f;

    load_chunk(A, W, m0, n0, 0, sa_u[0], sb_u[0], tid);
    load_chunk(A, W, m0, n0, 1, sa_u[1], sb_u[1], tid);

    for (int ch = 0; ch < GCHUNKS; ch++) {
        const int buf = ch & 1;
        CP_WAIT1();
        __syncthreads();

        const float* Ab = As[buf] + (wm * 32 + qrow) * LDT + 2 * qcol;
        const float* Bb = Bs[buf] + (wn * 64 + qrow) * LDT + 2 * qcol;

        #pragma unroll
        for (int kk = 0; kk < BK; kk += 8) {
            uint32_t af[2][4];
            #pragma unroll
            for (int mt = 0; mt < 2; mt++) {
                const float* p = Ab + mt * 16 * LDT + kk;
                float2 xa = *(const float2*)p;
                float2 xb = *(const float2*)(p + 8 * LDT);
                af[mt][0] = __float_as_uint(xa.x);
                af[mt][1] = __float_as_uint(xb.x);
                af[mt][2] = __float_as_uint(xa.y);
                af[mt][3] = __float_as_uint(xb.y);
            }
            uint32_t bf[8][2];
            #pragma unroll
            for (int nt = 0; nt < 8; nt++) {
                float2 y = *(const float2*)(Bb + nt * 8 * LDT + kk);
                bf[nt][0] = __float_as_uint(y.x);
                bf[nt][1] = __float_as_uint(y.y);
            }
            #pragma unroll
            for (int mt = 0; mt < 2; mt++)
                #pragma unroll
                for (int nt = 0; nt < 8; nt++)
                    mma_tf32_16x8x8(c[mt][nt], af[mt], bf[nt]);
        }

        __syncthreads();
        if (ch + 2 < GCHUNKS)
            load_chunk(A, W, m0, n0, ch + 2, sa_u[buf], sb_u[buf], tid);
    }
    CP_WAIT0();

    #pragma unroll
    for (int mt = 0; mt < 2; mt++) {
        #pragma unroll
        for (int half = 0; half < 2; half++) {
            const int m = m0 + wm * 32 + mt * 16 + half * 8 + qrow;
            #pragma unroll
            for (int nt = 0; nt < 8; nt++) {
                const int n = n0 + wn * 64 + nt * 8 + 2 * qcol;
                float v0 = c[mt][nt][half * 2 + 0];
                float v1 = c[mt][nt][half * 2 + 1];
                if (mode == 0) {
                    float2 bb = *(const float2*)(bias + n);
                    *(float2*)(O + (size_t)m * EMBED + n) =
                        make_float2(v0 + bb.x, v1 + bb.y);
                } else {
                    const int b = m >> 11, s = m & (SEQ - 1);
                    const int h = n >> 6, dd = n & 63;
                    if (mode == 3) {
                        // V: transposed [bh][d][s], seq sig8-permuted, tf32
                        int sp = (s & ~7) | sig8(s & 7);
                        float* baseT = O + (((size_t)(b * HEADS + h) * DK + dd) * SEQ + sp);
                        *(uint32_t*)baseT = f2tf32(v0);
                        *(uint32_t*)(baseT + SEQ) = f2tf32(v1);
                    } else {
                        // Q/K: [bh][s][d], d-perm within 8-groups, tf32-rounded
                        if (mode == 1) { v0 *= QSCALE; v1 *= QSCALE; }
                        int dp0 = (dd & ~7) | sig8(dd & 7);
                        int dp1 = ((dd + 1) & ~7) | sig8((dd + 1) & 7);
                        float* base = O + (((size_t)(b * HEADS + h) * SEQ + s) * DK);
                        *(uint32_t*)(base + dp0) = f2tf32(v0);
                        *(uint32_t*)(base + dp1) = f2tf32(v1);
                    }
                }
            }
        }
    }
}

__global__ __launch_bounds__(256, 2) void qkv_gemm()
{
    extern __shared__ __align__(16) float smg[];
    const int z = blockIdx.z;
    const float* A = (z == 0) ? g_xq : (z == 1) ? g_xk : g_xv;
    const float* W = (z == 0) ? g_wq : (z == 1) ? g_wk : g_wv;
    float* O = (z == 0) ? g_q : (z == 1) ? g_k : g_v;
    gemm_body(A, W, O, nullptr, z + 1, smg, blockIdx.x, blockIdx.y);
}

__global__ __launch_bounds__(256, 2) void out_gemm(const float* __restrict__ bias,
                                                   float* __restrict__ O)
{
    extern __shared__ __align__(16) float smg[];
    gemm_body(g_att, g_wo, O, bias, 0, smg, blockIdx.x, blockIdx.y);
}

// ---------------------------------------------------------------------------
// Tensor-core flash attention: CTA = 128 Q rows, 256 threads (8 warps),
// KV tiles of 64, K/V double-buffered (round-11 pipeline). log2-domain
// softmax (Q carries 0.125*log2e). Fully-masked warps skip compute.
// ---------------------------------------------------------------------------
#define AP 72
#define QROWS 128
#define ATTN_SMEM ((QROWS + 4 * 64) * AP * 4)   // 110592

__device__ __forceinline__ void load_q128(uint32_t dst, const float* __restrict__ src,
                                          int tid) {
    #pragma unroll
    for (int it = 0; it < 8; it++) {
        int seg = it * 256 + tid;
        int row = seg >> 4, chk = seg & 15;
        cp16(dst + (uint32_t)(row * AP + chk * 4) * 4u, src + row * 64 + chk * 4);
    }
}
__device__ __forceinline__ void load_k64(uint32_t dst, const float* __restrict__ src,
                                         int tid) {
    #pragma unroll
    for (int it = 0; it < 4; it++) {
        int seg = it * 256 + tid;
        int row = seg >> 4, chk = seg & 15;
        cp16(dst + (uint32_t)(row * AP + chk * 4) * 4u, src + row * 64 + chk * 4);
    }
}
__device__ __forceinline__ void load_v64(uint32_t dst, const float* __restrict__ src,
                                         int tid) {
    #pragma unroll
    for (int it = 0; it < 4; it++) {
        int seg = it * 256 + tid;
        int row = seg >> 4, chk = seg & 15;
        cp16(dst + (uint32_t)(row * AP + chk * 4) * 4u, src + (size_t)row * SEQ + chk * 4);
    }
}

__global__ __launch_bounds__(256, 2) void attn_mma()
{
    extern __shared__ __align__(16) float sm[];
    float* Qs  = sm;
    float* Ks0 = sm + QROWS * AP;
    float* Ks1 = Ks0 + 64 * AP;
    float* Vs0 = Ks1 + 64 * AP;
    float* Vs1 = Vs0 + 64 * AP;

    const int qt = (int)gridDim.x - 1 - (int)blockIdx.x;   // longest first
    const int bh = blockIdx.y;
    const int b = bh >> 4, h = bh & 15;
    const int tid = threadIdx.x, lane = tid & 31, w = tid >> 5;
    const int r = lane >> 2, c = lane & 3;

    const float* Qg = g_q + ((size_t)bh * SEQ + qt * QROWS) * DK;
    const float* Kg = g_k + (size_t)bh * SEQ * DK;
    const float* Vg = g_v + (size_t)bh * DK * SEQ;      // transposed

    load_q128(smem_to_u32(Qs), Qg, tid);
    CP_COMMIT();
    load_k64(smem_to_u32(Ks0), Kg, tid);
    load_v64(smem_to_u32(Vs0), Vg, tid);
    CP_COMMIT();

    float mr0 = -1e30f, mr1 = -1e30f, lr0 = 0.f, lr1 = 0.f;
    float o[8][4];
    #pragma unroll
    for (int nd = 0; nd < 8; nd++)
        #pragma unroll
        for (int j = 0; j < 4; j++) o[nd][j] = 0.f;

    const int wmin  = qt * QROWS + w * 16;      // warp's lowest Q row
    const int rowg0 = wmin + r;
    const int rowg1 = rowg0 + 8;
    const int srcA = (lane & ~3) | (c >> 1);
    const int srcB = srcA + 2;
    const bool oddc = (c & 1) != 0;

    const int ktmax = 2 * qt + 1;
    for (int kt = 0; kt <= ktmax; kt++) {
        const float* Kb = (kt & 1) ? Ks1 : Ks0;
        const float* Vb = (kt & 1) ? Vs1 : Vs0;
        CP_WAIT0();
        __syncthreads();
        if (kt < ktmax) {
            load_k64(smem_to_u32((kt & 1) ? Ks0 : Ks1), Kg + (size_t)(kt + 1) * 64 * DK, tid);
            load_v64(smem_to_u32((kt & 1) ? Vs0 : Vs1), Vg + (size_t)(kt + 1) * 64, tid);
            CP_COMMIT();
        }

        // warp fully above this KV tile (all masked) -> skip compute
        if (kt * 64 > wmin + 15) continue;

        // ---- S = Q K^T (scores already in log2 domain) ----
        float s[8][4];
        #pragma unroll
        for (int nt = 0; nt < 8; nt++)
            #pragma unroll
            for (int j = 0; j < 4; j++) s[nt][j] = 0.f;

        const float* Qb = Qs + (w * 16 + r) * AP + 2 * c;
        #pragma unroll
        for (int s8 = 0; s8 < 8; s8++) {
            float2 qa = *(const float2*)(Qb + 8 * s8);
            float2 qb = *(const float2*)(Qb + 8 * s8 + 8 * AP);
            uint32_t ah[4] = { __float_as_uint(qa.x), __float_as_uint(qb.x),
                               __float_as_uint(qa.y), __float_as_uint(qb.y) };
            #pragma unroll
            for (int nt = 0; nt < 8; nt++) {
                float2 kk = *(const float2*)(Kb + (nt * 8 + r) * AP + 8 * s8 + 2 * c);
                uint32_t bb[2] = { __float_as_uint(kk.x), __float_as_uint(kk.y) };
                mma_tf32_16x8x8(s[nt], ah, bb);
            }
        }

        // ---- mask, online softmax (log2 domain, ex2.approx) ----
        const bool diag = (kt * 64 + 63 > wmin);
        float mx0 = -1e30f, mx1 = -1e30f;
        #pragma unroll
        for (int nt = 0; nt < 8; nt++) {
            if (diag) {
                int colb = kt * 64 + nt * 8 + 2 * c;
                if (colb     > rowg0) s[nt][0] = -1e30f;
                if (colb + 1 > rowg0) s[nt][1] = -1e30f;
                if (colb     > rowg1) s[nt][2] = -1e30f;
                if (colb + 1 > rowg1) s[nt][3] = -1e30f;
            }
            mx0 = fmaxf(mx0, fmaxf(s[nt][0], s[nt][1]));
            mx1 = fmaxf(mx1, fmaxf(s[nt][2], s[nt][3]));
        }
        mx0 = fmaxf(mx0, __shfl_xor_sync(0xffffffffu, mx0, 1));
        mx0 = fmaxf(mx0, __shfl_xor_sync(0xffffffffu, mx0, 2));
        mx1 = fmaxf(mx1, __shfl_xor_sync(0xffffffffu, mx1, 1));
        mx1 = fmaxf(mx1, __shfl_xor_sync(0xffffffffu, mx1, 2));

        float nm0 = fmaxf(mr0, mx0), nm1 = fmaxf(mr1, mx1);
        float al0 = ex2f(mr0 - nm0), al1 = ex2f(mr1 - nm1);
        mr0 = nm0; mr1 = nm1;

        uint32_t pu[8][4];
        float rs0 = 0.f, rs1 = 0.f;
        #pragma unroll
        for (int nt = 0; nt < 8; nt++) {
            pu[nt][0] = f2tf32(ex2f(s[nt][0] - nm0));
            pu[nt][1] = f2tf32(ex2f(s[nt][1] - nm0));
            pu[nt][2] = f2tf32(ex2f(s[nt][2] - nm1));
            pu[nt][3] = f2tf32(ex2f(s[nt][3] - nm1));
            rs0 += __uint_as_float(pu[nt][0]) + __uint_as_float(pu[nt][1]);
            rs1 += __uint_as_float(pu[nt][2]) + __uint_as_float(pu[nt][3]);
        }
        rs0 += __shfl_xor_sync(0xffffffffu, rs0, 1);
        rs0 += __shfl_xor_sync(0xffffffffu, rs0, 2);
        rs1 += __shfl_xor_sync(0xffffffffu, rs1, 1);
        rs1 += __shfl_xor_sync(0xffffffffu, rs1, 2);
        lr0 = lr0 * al0 + rs0;
        lr1 = lr1 * al1 + rs1;
        #pragma unroll
        for (int nd = 0; nd < 8; nd++) {
            o[nd][0] *= al0; o[nd][1] *= al0;
            o[nd][2] *= al1; o[nd][3] *= al1;
        }

        // ---- O += P V : C-frag -> A-frag via quad shuffles; V LDS.64 ----
        #pragma unroll
        for (int g = 0; g < 8; g++) {
            uint32_t u0 = __shfl_sync(0xffffffffu, pu[g][0], srcA);
            uint32_t u1 = __shfl_sync(0xffffffffu, pu[g][1], srcA);
            uint32_t u2 = __shfl_sync(0xffffffffu, pu[g][2], srcA);
            uint32_t u3 = __shfl_sync(0xffffffffu, pu[g][3], srcA);
            uint32_t w0 = __shfl_sync(0xffffffffu, pu[g][0], srcB);
            uint32_t w1 = __shfl_sync(0xffffffffu, pu[g][1], srcB);
            uint32_t w2 = __shfl_sync(0xffffffffu, pu[g][2], srcB);
            uint32_t w3 = __shfl_sync(0xffffffffu, pu[g][3], srcB);
            uint32_t af[4];
            af[0] = oddc ? u1 : u0;
            af[1] = oddc ? u3 : u2;
            af[2] = oddc ? w1 : w0;
            af[3] = oddc ? w3 : w2;
            const float* Vr = Vb + r * AP + 8 * g + 2 * c;   // row d = nd*8 + r
            #pragma unroll
            for (int nd = 0; nd < 8; nd++) {
                float2 vv = *(const float2*)(Vr + nd * 8 * AP);
                uint32_t bb[2] = { __float_as_uint(vv.x), __float_as_uint(vv.y) };
                mma_tf32_16x8x8(o[nd], af, bb);
            }
        }
    }

    // ---- normalize, round to tf32, write [B,S,E] with e-perm ----
    float inv0 = 1.f / lr0, inv1 = 1.f / lr1;
    float* O0 = g_att + ((size_t)(b * SEQ + rowg0)) * EMBED + h * 64;
    float* O1 = g_att + ((size_t)(b * SEQ + rowg1)) * EMBED + h * 64;
    const int p0 = sig8(2 * c), p1 = sig8(2 * c + 1);
    #pragma unroll
    for (int nd = 0; nd < 8; nd++) {
        int d8 = nd * 8;
        *(uint32_t*)(O0 + d8 + p0) = f2tf32(o[nd][0] * inv0);
        *(uint32_t*)(O0 + d8 + p1) = f2tf32(o[nd][1] * inv0);
        *(uint32_t*)(O1 + d8 + p0) = f2tf32(o[nd][2] * inv1);
        *(uint32_t*)(O1 + d8 + p1) = f2tf32(o[nd][3] * inv1);
    }
}

// ---------------------------------------------------------------------------
extern "C" void kernel_launch(void* const* d_in, const int* in_sizes, int n_in,
                              void* d_out, int out_size)
{
    const float* key_   = (const float*)d_in[0];
    const float* query_ = (const float*)d_in[1];
    const float* value_ = (const float*)d_in[2];
    const float* Wq = (const float*)d_in[3];
    const float* Wk = (const float*)d_in[4];
    const float* Wv = (const float*)d_in[5];
    const float* Wo = (const float*)d_in[6];
    const float* bo = (const float*)d_in[7];
    float* out = (float*)d_out;

    cvt4_kernel<<<dim3(EMBED * EMBED / 1024, 4), 256>>>(Wq, Wk, Wv, Wo);
    prep_act_kernel<<<dim3(MTOT * EMBED / 1024, 3), 256>>>(query_, key_, value_);

    const int gemm_smem = 4 * TILE_F * (int)sizeof(float);   // 81920
    cudaFuncSetAttribute(qkv_gemm, cudaFuncAttributeMaxDynamicSharedMemorySize, gemm_smem);
    cudaFuncSetAttribute(out_gemm, cudaFuncAttributeMaxDynamicSharedMemorySize, gemm_smem);

    qkv_gemm<<<dim3(EMBED / BN, MTOT / BM, 3), 256, gemm_smem>>>();

    cudaFuncSetAttribute(attn_mma, cudaFuncAttributeMaxDynamicSharedMemorySize, ATTN_SMEM);
    attn_mma<<<dim3(SEQ / QROWS, BATCH * HEADS), 256, ATTN_SMEM>>>();

    out_gemm<<<dim3(EMBED / BN, MTOT / BM), 256, gemm_smem>>>(bo, out);
}

// round 13
// speedup vs baseline: 1.0552x; 1.0552x over previous
#include <cuda_runtime.h>
#include <cstdint>

#define EMBED 1024
#define HEADS 16
#define DK 64
#define BATCH 2
#define SEQ 2048
#define MTOT (BATCH*SEQ)   // 4096

// Q pre-scale: 1/sqrt(64) * log2(e) folded into the Q projection epilogue
#define QSCALE 0.1803368801111f

// ---------------------------------------------------------------------------
// Scratch
// ---------------------------------------------------------------------------
__device__ float g_q[(size_t)BATCH*HEADS*SEQ*DK];
__device__ float g_k[(size_t)BATCH*HEADS*SEQ*DK];
__device__ float g_v[(size_t)BATCH*HEADS*DK*SEQ];   // transposed [bh][d][s]
__device__ float g_att[(size_t)MTOT*EMBED];
__device__ float g_wq[(size_t)EMBED*EMBED];
__device__ float g_wk[(size_t)EMBED*EMBED];
__device__ float g_wv[(size_t)EMBED*EMBED];
__device__ float g_wo[(size_t)EMBED*EMBED];
__device__ float g_xq[(size_t)MTOT*EMBED];
__device__ float g_xk[(size_t)MTOT*EMBED];
__device__ float g_xv[(size_t)MTOT*EMBED];

// ---------------------------------------------------------------------------
// Helpers
// ---------------------------------------------------------------------------
__device__ __forceinline__ uint32_t smem_to_u32(const void* p) {
    uint32_t a;
    asm("{ .reg .u64 t; cvta.to.shared.u64 t, %1; cvt.u32.u64 %0, t; }"
        : "=r"(a) : "l"(p));
    return a;
}
__device__ __forceinline__ uint32_t f2tf32(float x) {
    uint32_t u;
    asm("cvt.rna.tf32.f32 %0, %1;" : "=r"(u) : "f"(x));
    return u;
}
__device__ __forceinline__ float ex2f(float x) {
    float y;
    asm("ex2.approx.f32 %0, %1;" : "=f"(y) : "f"(x));
    return y;
}
__device__ __forceinline__ void mma_tf32_16x8x8(float c[4], const uint32_t a[4],
                                                const uint32_t b[2]) {
    asm("mma.sync.aligned.m16n8k8.row.col.f32.tf32.tf32.f32 "
        "{%0,%1,%2,%3}, {%4,%5,%6,%7}, {%8,%9}, {%0,%1,%2,%3};"
        : "+f"(c[0]), "+f"(c[1]), "+f"(c[2]), "+f"(c[3])
        : "r"(a[0]), "r"(a[1]), "r"(a[2]), "r"(a[3]), "r"(b[0]), "r"(b[1]));
}
__device__ __forceinline__ void cp16(uint32_t dst, const void* src) {
    asm volatile("cp.async.cg.shared.global [%0], [%1], 16;" :: "r"(dst), "l"(src));
}
#define CP_COMMIT() asm volatile("cp.async.commit_group;" ::: "memory")
#define CP_WAIT1()  asm volatile("cp.async.wait_group 1;" ::: "memory")
#define CP_WAIT0()  asm volatile("cp.async.wait_group 0;" ::: "memory")

// within-8 permutation: original index b -> slot; pairs (b, b+4) land at (2b, 2b+1)
__device__ __host__ __forceinline__ int sig8(int b) { return ((b & 3) << 1) | (b >> 2); }

// ---------------------------------------------------------------------------
// Pre-passes: fp32 -> tf32 (rna) + sig8 k-axis permutation
// ---------------------------------------------------------------------------
__global__ void cvt4_kernel(const float* __restrict__ wq, const float* __restrict__ wk,
                            const float* __restrict__ wv, const float* __restrict__ wo) {
    const int sel = blockIdx.y;
    const float* in = (sel == 0) ? wq : (sel == 1) ? wk : (sel == 2) ? wv : wo;
    float* out = (sel == 0) ? g_wq : (sel == 1) ? g_wk : (sel == 2) ? g_wv : g_wo;
    size_t i = ((size_t)blockIdx.x * 256 + threadIdx.x) * 4;
    float4 v = *(const float4*)(in + i);
    size_t base = i & ~7ULL;
    int off = (int)(i & 7);
    *(uint32_t*)(out + base + sig8(off + 0)) = f2tf32(v.x);
    *(uint32_t*)(out + base + sig8(off + 1)) = f2tf32(v.y);
    *(uint32_t*)(out + base + sig8(off + 2)) = f2tf32(v.z);
    *(uint32_t*)(out + base + sig8(off + 3)) = f2tf32(v.w);
}

__global__ void prep_act_kernel(const float* __restrict__ q, const float* __restrict__ k,
                                const float* __restrict__ v) {
    const int sel = blockIdx.y;
    const float* in = (sel == 0) ? q : (sel == 1) ? k : v;
    float* out = (sel == 0) ? g_xq : (sel == 1) ? g_xk : g_xv;
    size_t i = ((size_t)blockIdx.x * 256 + threadIdx.x) * 4;
    float4 val = *(const float4*)(in + i);
    size_t base = i & ~7ULL;
    int off = (int)(i & 7);
    *(uint32_t*)(out + base + sig8(off + 0)) = f2tf32(val.x);
    *(uint32_t*)(out + base + sig8(off + 1)) = f2tf32(val.y);
    *(uint32_t*)(out + base + sig8(off + 2)) = f2tf32(val.z);
    *(uint32_t*)(out + base + sig8(off + 3)) = f2tf32(val.w);
}

// ---------------------------------------------------------------------------
// tf32 mma.sync GEMM body. A and W pre-rounded + k-permuted -> LDS.64 frags.
// mode: 0 = plain + bias; 1 = Q (scatter + d-perm, *QSCALE, tf32);
//       2 = K (scatter + d-perm + s-row-perm, tf32);
//       3 = V (transposed [bh][d][s], s-perm, tf32)
// ---------------------------------------------------------------------------
#define BM 128
#define BN 128
#define BK 32
#define LDT 40
#define TILE_F (BM * LDT)
#define GCHUNKS (EMBED / BK)

__device__ __forceinline__ void load_chunk(const float* __restrict__ A,
                                           const float* __restrict__ W,
                                           int m0, int n0, int c,
                                           uint32_t sa, uint32_t sb, int tid) {
    const float* Ab = A + (size_t)m0 * EMBED + c * BK;
    #pragma unroll
    for (int it = 0; it < 4; it++) {
        int seg = tid + it * 256;
        int r = seg >> 3, s8 = seg & 7;
        cp16(sa + r * (LDT * 4) + s8 * 16, Ab + (size_t)r * EMBED + s8 * 4);
    }
    const float* Wb = W + (size_t)n0 * EMBED + c * BK;
    #pragma unroll
    for (int it = 0; it < 4; it++) {
        int seg = tid + it * 256;
        int r = seg >> 3, s8 = seg & 7;
        cp16(sb + r * (LDT * 4) + s8 * 16, Wb + (size_t)r * EMBED + s8 * 4);
    }
    CP_COMMIT();
}

__device__ __forceinline__ void gemm_body(
    const float* __restrict__ A, const float* __restrict__ W,
    float* __restrict__ O, const float* __restrict__ bias, int mode,
    float* smg, int bx, int by)
{
    float* As[2] = { smg,            smg + 2 * TILE_F };
    float* Bs[2] = { smg + TILE_F,   smg + 3 * TILE_F };
    const uint32_t sa_u[2] = { smem_to_u32(As[0]), smem_to_u32(As[1]) };
    const uint32_t sb_u[2] = { smem_to_u32(Bs[0]), smem_to_u32(Bs[1]) };

    const int tid = threadIdx.x;
    const int lane = tid & 31;
    const int warp = tid >> 5;
    const int wm = warp >> 1;
    const int wn = warp & 1;
    const int qrow = lane >> 2;
    const int qcol = lane & 3;
    const int m0 = by * BM;
    const int n0 = bx * BN;

    float c[2][8][4];
    #pragma unroll
    for (int mt = 0; mt < 2; mt++)
        #pragma unroll
        for (int nt = 0; nt < 8; nt++)
            #pragma unroll
            for (int r = 0; r < 4; r++) c[mt][nt][r] = 0.f;

    load_chunk(A, W, m0, n0, 0, sa_u[0], sb_u[0], tid);
    load_chunk(A, W, m0, n0, 1, sa_u[1], sb_u[1], tid);

    for (int ch = 0; ch < GCHUNKS; ch++) {
        const int buf = ch & 1;
        CP_WAIT1();
        __syncthreads();

        const float* Ab = As[buf] + (wm * 32 + qrow) * LDT + 2 * qcol;
        const float* Bb = Bs[buf] + (wn * 64 + qrow) * LDT + 2 * qcol;

        #pragma unroll
        for (int kk = 0; kk < BK; kk += 8) {
            uint32_t af[2][4];
            #pragma unroll
            for (int mt = 0; mt < 2; mt++) {
                const float* p = Ab + mt * 16 * LDT + kk;
                float2 xa = *(const float2*)p;
                float2 xb = *(const float2*)(p + 8 * LDT);
                af[mt][0] = __float_as_uint(xa.x);
                af[mt][1] = __float_as_uint(xb.x);
                af[mt][2] = __float_as_uint(xa.y);
                af[mt][3] = __float_as_uint(xb.y);
            }
            uint32_t bf[8][2];
            #pragma unroll
            for (int nt = 0; nt < 8; nt++) {
                float2 y = *(const float2*)(Bb + nt * 8 * LDT + kk);
                bf[nt][0] = __float_as_uint(y.x);
                bf[nt][1] = __float_as_uint(y.y);
            }
            #pragma unroll
            for (int mt = 0; mt < 2; mt++)
                #pragma unroll
                for (int nt = 0; nt < 8; nt++)
                    mma_tf32_16x8x8(c[mt][nt], af[mt], bf[nt]);
        }

        __syncthreads();
        if (ch + 2 < GCHUNKS)
            load_chunk(A, W, m0, n0, ch + 2, sa_u[buf], sb_u[buf], tid);
    }
    CP_WAIT0();

    #pragma unroll
    for (int mt = 0; mt < 2; mt++) {
        #pragma unroll
        for (int half = 0; half < 2; half++) {
            const int m = m0 + wm * 32 + mt * 16 + half * 8 + qrow;
            #pragma unroll
            for (int nt = 0; nt < 8; nt++) {
                const int n = n0 + wn * 64 + nt * 8 + 2 * qcol;
                float v0 = c[mt][nt][half * 2 + 0];
                float v1 = c[mt][nt][half * 2 + 1];
                if (mode == 0) {
                    float2 bb = *(const float2*)(bias + n);
                    *(float2*)(O + (size_t)m * EMBED + n) =
                        make_float2(v0 + bb.x, v1 + bb.y);
                } else {
                    const int b = m >> 11, s = m & (SEQ - 1);
                    const int h = n >> 6, dd = n & 63;
                    if (mode == 3) {
                        // V: transposed [bh][d][s], seq sig8-permuted, tf32
                        int sp = (s & ~7) | sig8(s & 7);
                        float* baseT = O + (((size_t)(b * HEADS + h) * DK + dd) * SEQ + sp);
                        *(uint32_t*)baseT = f2tf32(v0);
                        *(uint32_t*)(baseT + SEQ) = f2tf32(v1);
                    } else {
                        // Q/K: [bh][s][d], d-perm within 8-groups, tf32-rounded
                        float s0 = v0, s1 = v1;
                        int srow = s;
                        if (mode == 1) { s0 *= QSCALE; s1 *= QSCALE; }
                        if (mode == 2) { srow = (s & ~7) | sig8(s & 7); }  // K row perm
                        int dp0 = (dd & ~7) | sig8(dd & 7);
                        int dp1 = ((dd + 1) & ~7) | sig8((dd + 1) & 7);
                        float* base = O + (((size_t)(b * HEADS + h) * SEQ + srow) * DK);
                        *(uint32_t*)(base + dp0) = f2tf32(s0);
                        *(uint32_t*)(base + dp1) = f2tf32(s1);
                    }
                }
            }
        }
    }
}

__global__ __launch_bounds__(256, 2) void qkv_gemm()
{
    extern __shared__ __align__(16) float smg[];
    const int z = blockIdx.z;
    const float* A = (z == 0) ? g_xq : (z == 1) ? g_xk : g_xv;
    const float* W = (z == 0) ? g_wq : (z == 1) ? g_wk : g_wv;
    float* O = (z == 0) ? g_q : (z == 1) ? g_k : g_v;
    gemm_body(A, W, O, nullptr, z + 1, smg, blockIdx.x, blockIdx.y);
}

__global__ __launch_bounds__(256, 2) void out_gemm(const float* __restrict__ bias,
                                                   float* __restrict__ O)
{
    extern __shared__ __align__(16) float smg[];
    gemm_body(g_att, g_wo, O, bias, 0, smg, blockIdx.x, blockIdx.y);
}

// ---------------------------------------------------------------------------
// Tensor-core flash attention (round-11 pipeline): CTA = 64 Q rows, 128 thr,
// K/V double-buffered, log2-domain softmax. PV computed TRANSPOSED:
// O^T = V^T * P^T -- the S C-fragment is reused directly as the PV B-fragment
// (K seq-rows are sig8-permuted by the producer GEMM), eliminating all
// C-frag->A-frag shuffles.
// ---------------------------------------------------------------------------
#define AP 72
#define ATTN_SMEM (5 * 64 * AP * 4)   // 92160

__device__ __forceinline__ void load_qk(uint32_t dst, const float* __restrict__ src,
                                        int tid) {
    #pragma unroll
    for (int it = 0; it < 8; it++) {
        int seg = it * 128 + tid;
        int row = seg >> 4, chk = seg & 15;
        cp16(dst + (uint32_t)(row * AP + chk * 4) * 4u, src + row * 64 + chk * 4);
    }
}
__device__ __forceinline__ void load_vt(uint32_t dst, const float* __restrict__ src,
                                        int tid) {
    #pragma unroll
    for (int it = 0; it < 8; it++) {
        int seg = it * 128 + tid;
        int row = seg >> 4, chk = seg & 15;
        cp16(dst + (uint32_t)(row * AP + chk * 4) * 4u, src + (size_t)row * SEQ + chk * 4);
    }
}

__global__ __launch_bounds__(128) void attn_mma()
{
    extern __shared__ __align__(16) float sm[];
    float* Qs  = sm;
    float* Ks0 = sm + 64 * AP;
    float* Ks1 = Ks0 + 64 * AP;
    float* Vs0 = Ks1 + 64 * AP;
    float* Vs1 = Vs0 + 64 * AP;

    const int qt = (int)gridDim.x - 1 - (int)blockIdx.x;   // longest first
    const int bh = blockIdx.y;
    const int b = bh >> 4, h = bh & 15;
    const int tid = threadIdx.x, lane = tid & 31, w = tid >> 5;
    const int r = lane >> 2, c = lane & 3;

    const float* Qg = g_q + ((size_t)bh * SEQ + qt * 64) * DK;
    const float* Kg = g_k + (size_t)bh * SEQ * DK;
    const float* Vg = g_v + (size_t)bh * DK * SEQ;      // transposed

    load_qk(smem_to_u32(Qs), Qg, tid);
    CP_COMMIT();
    load_qk(smem_to_u32(Ks0), Kg, tid);
    load_vt(smem_to_u32(Vs0), Vg, tid);
    CP_COMMIT();

    float mr0 = -1e30f, mr1 = -1e30f, lr0 = 0.f, lr1 = 0.f;
    // O^T accumulators: oT[mt][qh][4], mt = 16-d slab, qh = q rows 0-7 / 8-15
    float oT[4][2][4];
    #pragma unroll
    for (int mt = 0; mt < 4; mt++)
        #pragma unroll
        for (int qh = 0; qh < 2; qh++)
            #pragma unroll
            for (int j = 0; j < 4; j++) oT[mt][qh][j] = 0.f;

    const int rowg0 = qt * 64 + w * 16 + r;
    const int rowg1 = rowg0 + 8;
    const int sl0 = 9 * c;       // lane of q-row 2c (keep own c)
    const int sl1 = 9 * c + 4;   // lane of q-row 2c+1

    for (int kt = 0; kt <= qt; kt++) {
        const float* Kb = (kt & 1) ? Ks1 : Ks0;
        const float* Vb = (kt & 1) ? Vs1 : Vs0;
        CP_WAIT0();
        __syncthreads();
        if (kt < qt) {
            load_qk(smem_to_u32((kt & 1) ? Ks0 : Ks1), Kg + (size_t)(kt + 1) * 64 * DK, tid);
            load_vt(smem_to_u32((kt & 1) ? Vs0 : Vs1), Vg + (size_t)(kt + 1) * 64, tid);
            CP_COMMIT();
        }

        // ---- S = Q K^T (log2 domain; K rows sig8-permuted in gmem) ----
        float s[8][4];
        #pragma unroll
        for (int nt = 0; nt < 8; nt++)
            #pragma unroll
            for (int j = 0; j < 4; j++) s[nt][j] = 0.f;

        const float* Qb = Qs + (w * 16 + r) * AP + 2 * c;
        #pragma unroll
        for (int s8 = 0; s8 < 8; s8++) {
            float2 qa = *(const float2*)(Qb + 8 * s8);
            float2 qb = *(const float2*)(Qb + 8 * s8 + 8 * AP);
            uint32_t ah[4] = { __float_as_uint(qa.x), __float_as_uint(qb.x),
                               __float_as_uint(qa.y), __float_as_uint(qb.y) };
            #pragma unroll
            for (int nt = 0; nt < 8; nt++) {
                float2 kk = *(const float2*)(Kb + (nt * 8 + r) * AP + 8 * s8 + 2 * c);
                uint32_t bb[2] = { __float_as_uint(kk.x), __float_as_uint(kk.y) };
                mma_tf32_16x8x8(s[nt], ah, bb);
            }
        }

        // ---- mask, online softmax (C-frag col n=2c holds s=c; n=2c+1 holds s=c+4) ----
        const bool diag = (kt == qt);
        float mx0 = -1e30f, mx1 = -1e30f;
        #pragma unroll
        for (int nt = 0; nt < 8; nt++) {
            if (diag) {
                int sb0 = kt * 64 + nt * 8 + c;
                int sb1 = sb0 + 4;
                if (sb0 > rowg0) s[nt][0] = -1e30f;
                if (sb1 > rowg0) s[nt][1] = -1e30f;
                if (sb0 > rowg1) s[nt][2] = -1e30f;
                if (sb1 > rowg1) s[nt][3] = -1e30f;
            }
            mx0 = fmaxf(mx0, fmaxf(s[nt][0], s[nt][1]));
            mx1 = fmaxf(mx1, fmaxf(s[nt][2], s[nt][3]));
        }
        mx0 = fmaxf(mx0, __shfl_xor_sync(0xffffffffu, mx0, 1));
        mx0 = fmaxf(mx0, __shfl_xor_sync(0xffffffffu, mx0, 2));
        mx1 = fmaxf(mx1, __shfl_xor_sync(0xffffffffu, mx1, 1));
        mx1 = fmaxf(mx1, __shfl_xor_sync(0xffffffffu, mx1, 2));

        float nm0 = fmaxf(mr0, mx0), nm1 = fmaxf(mr1, mx1);
        float al0 = ex2f(mr0 - nm0), al1 = ex2f(mr1 - nm1);
        mr0 = nm0; mr1 = nm1;

        uint32_t pu[8][4];
        float rs0 = 0.f, rs1 = 0.f;
        #pragma unroll
        for (int nt = 0; nt < 8; nt++) {
            pu[nt][0] = f2tf32(ex2f(s[nt][0] - nm0));
            pu[nt][1] = f2tf32(ex2f(s[nt][1] - nm0));
            pu[nt][2] = f2tf32(ex2f(s[nt][2] - nm1));
            pu[nt][3] = f2tf32(ex2f(s[nt][3] - nm1));
            rs0 += __uint_as_float(pu[nt][0]) + __uint_as_float(pu[nt][1]);
            rs1 += __uint_as_float(pu[nt][2]) + __uint_as_float(pu[nt][3]);
        }
        rs0 += __shfl_xor_sync(0xffffffffu, rs0, 1);
        rs0 += __shfl_xor_sync(0xffffffffu, rs0, 2);
        rs1 += __shfl_xor_sync(0xffffffffu, rs1, 1);
        rs1 += __shfl_xor_sync(0xffffffffu, rs1, 2);
        lr0 = lr0 * al0 + rs0;
        lr1 = lr1 * al1 + rs1;

        // ---- rescale O^T: alphas broadcast along the n (q) axis ----
        float aq0 = __shfl_sync(0xffffffffu, al0, sl0);
        float aq1 = __shfl_sync(0xffffffffu, al0, sl1);
        float aq2 = __shfl_sync(0xffffffffu, al1, sl0);
        float aq3 = __shfl_sync(0xffffffffu, al1, sl1);
        #pragma unroll
        for (int mt = 0; mt < 4; mt++) {
            oT[mt][0][0] *= aq0; oT[mt][0][1] *= aq1;
            oT[mt][0][2] *= aq0; oT[mt][0][3] *= aq1;
            oT[mt][1][0] *= aq2; oT[mt][1][1] *= aq3;
            oT[mt][1][2] *= aq2; oT[mt][1][3] *= aq3;
        }

        // ---- O^T += V^T P^T : V^T as A-frag (LDS.64), S C-frag as B-frag ----
        #pragma unroll
        for (int g = 0; g < 8; g++) {
            #pragma unroll
            for (int mt = 0; mt < 4; mt++) {
                const float* Va = Vb + (mt * 16 + r) * AP + 8 * g + 2 * c;
                float2 v0 = *(const float2*)Va;
                float2 v1 = *(const float2*)(Va + 8 * AP);
                uint32_t av[4] = { __float_as_uint(v0.x), __float_as_uint(v1.x),
                                   __float_as_uint(v0.y), __float_as_uint(v1.y) };
                uint32_t b0[2] = { pu[g][0], pu[g][1] };
                uint32_t b1[2] = { pu[g][2], pu[g][3] };
                mma_tf32_16x8x8(oT[mt][0], av, b0);
                mma_tf32_16x8x8(oT[mt][1], av, b1);
            }
        }
    }

    // ---- normalize (inv broadcast along n), round to tf32, write [B,S,E] ----
    float inv0 = 1.f / lr0, inv1 = 1.f / lr1;
    float iq0 = __shfl_sync(0xffffffffu, inv0, sl0);
    float iq1 = __shfl_sync(0xffffffffu, inv0, sl1);
    float iq2 = __shfl_sync(0xffffffffu, inv1, sl0);
    float iq3 = __shfl_sync(0xffffffffu, inv1, sl1);

    const int qb = qt * 64 + w * 16;
    const int slot = sig8(r);
    float* Arow0 = g_att + ((size_t)(b * SEQ + qb + 2 * c))     * EMBED + h * 64;
    float* Arow1 = g_att + ((size_t)(b * SEQ + qb + 2 * c + 1)) * EMBED + h * 64;
    float* Arow2 = Arow0 + (size_t)8 * EMBED;
    float* Arow3 = Arow1 + (size_t)8 * EMBED;
    #pragma unroll
    for (int mt = 0; mt < 4; mt++) {
        int d0 = mt * 16 + slot;
        int d1 = d0 + 8;
        *(uint32_t*)(Arow0 + d0) = f2tf32(oT[mt][0][0] * iq0);
        *(uint32_t*)(Arow1 + d0) = f2tf32(oT[mt][0][1] * iq1);
        *(uint32_t*)(Arow0 + d1) = f2tf32(oT[mt][0][2] * iq0);
        *(uint32_t*)(Arow1 + d1) = f2tf32(oT[mt][0][3] * iq1);
        *(uint32_t*)(Arow2 + d0) = f2tf32(oT[mt][1][0] * iq2);
        *(uint32_t*)(Arow3 + d0) = f2tf32(oT[mt][1][1] * iq3);
        *(uint32_t*)(Arow2 + d1) = f2tf32(oT[mt][1][2] * iq2);
        *(uint32_t*)(Arow3 + d1) = f2tf32(oT[mt][1][3] * iq3);
    }
}

// ---------------------------------------------------------------------------
extern "C" void kernel_launch(void* const* d_in, const int* in_sizes, int n_in,
                              void* d_out, int out_size)
{
    const float* key_   = (const float*)d_in[0];
    const float* query_ = (const float*)d_in[1];
    const float* value_ = (const float*)d_in[2];
    const float* Wq = (const float*)d_in[3];
    const float* Wk = (const float*)d_in[4];
    const float* Wv = (const float*)d_in[5];
    const float* Wo = (const float*)d_in[6];
    const float* bo = (const float*)d_in[7];
    float* out = (float*)d_out;

    cvt4_kernel<<<dim3(EMBED * EMBED / 1024, 4), 256>>>(Wq, Wk, Wv, Wo);
    prep_act_kernel<<<dim3(MTOT * EMBED / 1024, 3), 256>>>(query_, key_, value_);

    const int gemm_smem = 4 * TILE_F * (int)sizeof(float);   // 81920
    cudaFuncSetAttribute(qkv_gemm, cudaFuncAttributeMaxDynamicSharedMemorySize, gemm_smem);
    cudaFuncSetAttribute(out_gemm, cudaFuncAttributeMaxDynamicSharedMemorySize, gemm_smem);

    qkv_gemm<<<dim3(EMBED / BN, MTOT / BM, 3), 256, gemm_smem>>>();

    cudaFuncSetAttribute(attn_mma, cudaFuncAttributeMaxDynamicSharedMemorySize, ATTN_SMEM);
    attn_mma<<<dim3(SEQ / 64, BATCH * HEADS), 128, ATTN_SMEM>>>();

    out_gemm<<<dim3(EMBED / BN, MTOT / BM), 256, gemm_smem>>>(bo, out);
}